// round 15
// baseline (speedup 1.0000x reference)
#include <cuda_runtime.h>
#include <cuda_bf16.h>
#include <math.h>

#define DIMN 3072
#define HEADS 24
#define HD 128
#define BATCH 2
#define S_IMG 1024
#define S_TXT 512
#define SEQ 1536
#define SCALE 0.08838834764831845f   // 1/sqrt(128)
#define M2 (DIMN * DIMN)

// ---------------- scratch ----------------
__device__ float g_qbuf[(size_t)BATCH * SEQ * DIMN];
__device__ float g_kbuf[(size_t)BATCH * SEQ * DIMN];
__device__ float g_vtbuf[(size_t)BATCH * SEQ * DIMN];   // V transposed: [b][h][d][seq]
__device__ float g_obuf[(size_t)BATCH * SEQ * DIMN];
__device__ float g_wtf[(size_t)8 * M2];                 // tf32 weights TRANSPOSED [n][k]
__device__ float g_xtf[(size_t)BATCH * S_IMG * DIMN];
__device__ float g_ctxtf[(size_t)BATCH * S_TXT * DIMN];

__device__ __forceinline__ unsigned f2tf(float f) {
    unsigned u;
    asm("cvt.rna.tf32.f32 %0, %1;" : "=r"(u) : "f"(f));
    return u;
}
__device__ __forceinline__ void mma_tf32(float& d0, float& d1, float& d2, float& d3,
                                         unsigned a0, unsigned a1, unsigned a2, unsigned a3,
                                         unsigned b0, unsigned b1)
{
    asm volatile("mma.sync.aligned.m16n8k8.row.col.f32.tf32.tf32.f32 "
                 "{%0,%1,%2,%3}, {%4,%5,%6,%7}, {%8,%9}, {%0,%1,%2,%3};\n"
                 : "+f"(d0), "+f"(d1), "+f"(d2), "+f"(d3)
                 : "r"(a0), "r"(a1), "r"(a2), "r"(a3), "r"(b0), "r"(b1));
}
__device__ __forceinline__ unsigned s2u(const void* p) {
    unsigned r;
    asm("{.reg .u64 t; cvta.to.shared.u64 t, %1; cvt.u32.u64 %0, t;}" : "=r"(r) : "l"(p));
    return r;
}
__device__ __forceinline__ void cpa16(unsigned dst, const void* src) {
    asm volatile("cp.async.cg.shared.global [%0], [%1], 16;" :: "r"(dst), "l"(src));
}
__device__ __forceinline__ void cp_commit() { asm volatile("cp.async.commit_group;"); }
template <int N> __device__ __forceinline__ void cp_wait() {
    asm volatile("cp.async.wait_group %0;" :: "n"(N));
}
__device__ __forceinline__ void ldm_x4(unsigned& r0, unsigned& r1, unsigned& r2, unsigned& r3,
                                       unsigned addr)
{
    asm volatile("ldmatrix.sync.aligned.m8n8.x4.shared.b16 {%0,%1,%2,%3}, [%4];"
                 : "=r"(r0), "=r"(r1), "=r"(r2), "=r"(r3) : "r"(addr));
}

// ---------------- pre-passes ----------------
struct WtCfg { const float* in[8]; float* out[8]; };

// transpose + tf32: in [k][n] -> out [n][k], float4 coalesced both sides
__global__ __launch_bounds__(256) void wtrans_cvt(WtCfg p)
{
    const float* in = p.in[blockIdx.z];
    float* out = p.out[blockIdx.z];
    __shared__ float ts[32][132];          // [k][n] tile, padded rows
    const int n0 = blockIdx.x * 128, k0 = blockIdx.y * 32;
    const int t = threadIdx.x;
    #pragma unroll
    for (int i = 0; i < 4; i++) {
        int kr = (t >> 5) + i * 8;
        float4 v = *(const float4*)(in + (size_t)(k0 + kr) * DIMN + n0 + (t & 31) * 4);
        *(float4*)&ts[kr][(t & 31) * 4] = v;
    }
    __syncthreads();
    #pragma unroll
    for (int jj = 0; jj < 4; jj++) {
        int nr = jj * 32 + (t >> 3);
        int kc = (t & 7) * 4;
        float4 o;
        o.x = __uint_as_float(f2tf(ts[kc + 0][nr]));
        o.y = __uint_as_float(f2tf(ts[kc + 1][nr]));
        o.z = __uint_as_float(f2tf(ts[kc + 2][nr]));
        o.w = __uint_as_float(f2tf(ts[kc + 3][nr]));
        *(float4*)(out + (size_t)(n0 + nr) * DIMN + k0 + kc) = o;
    }
}

struct CvAll { const float* in[2]; float* out[2]; int n4[2]; };
__global__ __launch_bounds__(256) void cvt_all(CvAll p)
{
    const float* in = p.in[blockIdx.y];
    float* out = p.out[blockIdx.y];
    const int n4 = p.n4[blockIdx.y];
    int i = blockIdx.x * blockDim.x + threadIdx.x;
    int stride = gridDim.x * blockDim.x;
    for (; i < n4; i += stride) {
        float4 v = ((const float4*)in)[i];
        float4 o;
        o.x = __uint_as_float(f2tf(v.x));
        o.y = __uint_as_float(f2tf(v.y));
        o.z = __uint_as_float(f2tf(v.z));
        o.w = __uint_as_float(f2tf(v.w));
        ((float4*)out)[i] = o;
    }
}

// ---------------- tf32 GEMM: full-ldmatrix body (W^T), 2 CTAs/SM ----------------
#define TLD 36
#define NSTAGE 3
#define ASTAGE (128 * TLD)
#define BSTAGE (128 * TLD)

struct GemmCfg {
    const float* A[2];
    const float* W[6];      // idx = z + 3*half
    const float* bias[6];
    float* C[6];
    int S[2], isb[2], ioff[2], osb[2], ooff[2];
    int ysplit, cvt_mask, vt_mask;
};

__global__ __launch_bounds__(256, 2) void gemm_tf32(GemmCfg p)
{
    extern __shared__ float sm[];
    float* As = sm;
    float* Bs = sm + NSTAGE * ASTAGE;

    const int z = blockIdx.z;
    const int half = (blockIdx.y >= p.ysplit) ? 1 : 0;
    const int yy = blockIdx.y - (half ? p.ysplit : 0);
    const int wi = z + 3 * half;
    const float* A    = p.A[half];
    const float* W    = p.W[wi];
    const float* bias = p.bias[wi];
    float* C          = p.C[wi];
    const int S_part = p.S[half], in_sb = p.isb[half], in_off = p.ioff[half];
    const int out_sb = p.osb[half], out_off = p.ooff[half];
    const bool do_cvt = (p.cvt_mask >> z) & 1;
    const bool do_vt  = (p.vt_mask >> z) & 1;

    const int t = threadIdx.x;
    const int lane = t & 31, w = t >> 5;
    const int g = lane >> 2, tig = lane & 3;
    const int wm = w >> 2, wn = w & 3;          // 2x4 warps, warp tile 64x32
    const int bm = yy * 128;
    const int bn = blockIdx.x * 128;

    const float* Aptr[4];
    #pragma unroll
    for (int j = 0; j < 4; j++) {
        int r = 32 * j + (t >> 3);
        int gr = bm + r;
        int ab = gr / S_part, as_ = gr - ab * S_part;
        Aptr[j] = A + (size_t)(ab * in_sb + in_off + as_) * DIMN + ((t & 7) << 2);
    }
    const float* Bptr[4];                        // W^T rows = n
    #pragma unroll
    for (int j = 0; j < 4; j++) {
        int r = 32 * j + (t >> 3);
        Bptr[j] = W + (size_t)(bn + r) * DIMN + ((t & 7) << 2);
    }

    const unsigned a_base = s2u(As);
    const unsigned b_base = s2u(Bs);
    unsigned a_off[4], b_off[4];
    #pragma unroll
    for (int j = 0; j < 4; j++) {
        unsigned o = (unsigned)(((32 * j + (t >> 3)) * TLD + ((t & 7) << 2)) * 4);
        a_off[j] = a_base + o;
        b_off[j] = b_base + o;
    }
    const unsigned a_lm = a_base +
        (unsigned)(((wm * 64 + (lane & 15)) * TLD + ((lane >> 4) << 2)) * 4);
    const unsigned b_lm = b_base +
        (unsigned)(((wn * 32 + (lane & 7) + ((lane >> 4) << 3)) * TLD + (((lane >> 3) & 1) << 2)) * 4);

    const int NITER = DIMN / 32;                // 96

    #pragma unroll
    for (int s = 0; s < 2; s++) {
        int k0 = s * 32;
        #pragma unroll
        for (int j = 0; j < 4; j++) cpa16(a_off[j] + s * ASTAGE * 4, Aptr[j] + k0);
        #pragma unroll
        for (int j = 0; j < 4; j++) cpa16(b_off[j] + s * BSTAGE * 4, Bptr[j] + k0);
        cp_commit();
    }

    float acc[4][4][4];
    #pragma unroll
    for (int mt = 0; mt < 4; mt++)
        #pragma unroll
        for (int nt = 0; nt < 4; nt++)
            #pragma unroll
            for (int i = 0; i < 4; i++) acc[mt][nt][i] = 0.f;

    int st = 0;
    for (int it = 0; it < NITER; it++) {
        // tail: drain fully on last iteration (no group committed after it)
        if (it == NITER - 1) cp_wait<0>(); else cp_wait<1>();
        __syncthreads();

        const unsigned a_st = a_lm + (unsigned)(st * ASTAGE * 4);
        const unsigned b_st = b_lm + (unsigned)(st * BSTAGE * 4);
        #pragma unroll
        for (int ks = 0; ks < 4; ks++) {
            unsigned a[4][4];
            #pragma unroll
            for (int mt = 0; mt < 4; mt++)
                ldm_x4(a[mt][0], a[mt][1], a[mt][2], a[mt][3],
                       a_st + (unsigned)(mt * 16 * TLD * 4 + ks * 32));
            unsigned bf[2][4];
            #pragma unroll
            for (int ntp = 0; ntp < 2; ntp++)
                ldm_x4(bf[ntp][0], bf[ntp][1], bf[ntp][2], bf[ntp][3],
                       b_st + (unsigned)(ntp * 16 * TLD * 4 + ks * 32));
            #pragma unroll
            for (int mt = 0; mt < 4; mt++) {
                mma_tf32(acc[mt][0][0], acc[mt][0][1], acc[mt][0][2], acc[mt][0][3],
                         a[mt][0], a[mt][1], a[mt][2], a[mt][3], bf[0][0], bf[0][1]);
                mma_tf32(acc[mt][1][0], acc[mt][1][1], acc[mt][1][2], acc[mt][1][3],
                         a[mt][0], a[mt][1], a[mt][2], a[mt][3], bf[0][2], bf[0][3]);
                mma_tf32(acc[mt][2][0], acc[mt][2][1], acc[mt][2][2], acc[mt][2][3],
                         a[mt][0], a[mt][1], a[mt][2], a[mt][3], bf[1][0], bf[1][1]);
                mma_tf32(acc[mt][3][0], acc[mt][3][1], acc[mt][3][2], acc[mt][3][3],
                         a[mt][0], a[mt][1], a[mt][2], a[mt][3], bf[1][2], bf[1][3]);
            }
        }

        if (it + 2 < NITER) {
            int k0 = (it + 2) * 32;
            int ns = (st + 2) % NSTAGE;
            #pragma unroll
            for (int j = 0; j < 4; j++) cpa16(a_off[j] + ns * ASTAGE * 4, Aptr[j] + k0);
            #pragma unroll
            for (int j = 0; j < 4; j++) cpa16(b_off[j] + ns * BSTAGE * 4, Bptr[j] + k0);
            cp_commit();
        }
        st = (st + 1) % NSTAGE;
    }

    #pragma unroll
    for (int mt = 0; mt < 4; mt++) {
        int r0 = bm + wm * 64 + mt * 16 + g;
        int r1 = r0 + 8;
        int cb0 = r0 / S_part, cs0 = r0 - cb0 * S_part;
        int cb1 = r1 / S_part, cs1 = r1 - cb1 * S_part;
        if (do_vt) {
            int s0 = out_off + cs0, s1 = out_off + cs1;
            #pragma unroll
            for (int nt = 0; nt < 4; nt++) {
                int col = bn + wn * 32 + nt * 8 + 2 * tig;
                int hh = col >> 7, d = col & 127;
                float bv0 = bias[col], bv1 = bias[col + 1];
                float* p0 = C + (((size_t)cb0 * HEADS + hh) * HD + d) * SEQ;
                float* p1 = C + (((size_t)cb1 * HEADS + hh) * HD + d) * SEQ;
                p0[s0]       = __uint_as_float(f2tf(acc[mt][nt][0] + bv0));
                p0[SEQ + s0] = __uint_as_float(f2tf(acc[mt][nt][1] + bv1));
                p1[s1]       = __uint_as_float(f2tf(acc[mt][nt][2] + bv0));
                p1[SEQ + s1] = __uint_as_float(f2tf(acc[mt][nt][3] + bv1));
            }
        } else {
            float* C0r = C + (size_t)(cb0 * out_sb + out_off + cs0) * DIMN;
            float* C1r = C + (size_t)(cb1 * out_sb + out_off + cs1) * DIMN;
            #pragma unroll
            for (int nt = 0; nt < 4; nt++) {
                int col = bn + wn * 32 + nt * 8 + 2 * tig;
                float bv0 = bias[col], bv1 = bias[col + 1];
                float v00 = acc[mt][nt][0] + bv0, v01 = acc[mt][nt][1] + bv1;
                float v10 = acc[mt][nt][2] + bv0, v11 = acc[mt][nt][3] + bv1;
                if (do_cvt) {
                    v00 = __uint_as_float(f2tf(v00)); v01 = __uint_as_float(f2tf(v01));
                    v10 = __uint_as_float(f2tf(v10)); v11 = __uint_as_float(f2tf(v11));
                }
                *(float2*)(C0r + col) = make_float2(v00, v01);
                *(float2*)(C1r + col) = make_float2(v10, v11);
            }
        }
    }
}

// ---------------- per-head RMSNorm + RoPE, batched (writes tf32; Q pre-scaled) ----------------
__global__ __launch_bounds__(256) void rmsrope_kernel(
    float* __restrict__ q, float* __restrict__ k,
    const float* __restrict__ cosb, const float* __restrict__ sinb,
    const float* __restrict__ gq, const float* __restrict__ gqc,
    const float* __restrict__ gk, const float* __restrict__ gkc)
{
    const int s = blockIdx.x;
    const int b = blockIdx.y;
    const int w = threadIdx.x >> 5, lane = threadIdx.x & 31;
    const size_t rowbase = ((size_t)(b * SEQ + s)) * DIMN;
    const bool txt = s < S_TXT;

    float2 cs = *(const float2*)(cosb + s * 64 + lane * 2);
    float2 sn = *(const float2*)(sinb + s * 64 + lane * 2);

    #pragma unroll
    for (int i = 0; i < 6; i++) {
        int inst = w * 6 + i;
        int which = inst / HEADS;
        int h = inst - which * HEADS;
        float* buf = which ? k : q;
        const float* gg = which ? (txt ? gkc : gk) : (txt ? gqc : gq);
        float post = which ? 1.0f : SCALE;

        float4 v = *(const float4*)(buf + rowbase + h * HD + lane * 4);
        float ss = v.x * v.x + v.y * v.y + v.z * v.z + v.w * v.w;
        #pragma unroll
        for (int o = 16; o; o >>= 1) ss += __shfl_xor_sync(0xffffffffu, ss, o);
        float r = rsqrtf(ss * (1.0f / HD) + 1e-6f);
        float4 gv = *(const float4*)(gg + lane * 4);
        float n0 = v.x * r * gv.x, n1 = v.y * r * gv.y;
        float n2 = v.z * r * gv.z, n3 = v.w * r * gv.w;
        float4 o4;
        o4.x = __uint_as_float(f2tf((n0 * cs.x - n1 * sn.x) * post));
        o4.y = __uint_as_float(f2tf((n0 * sn.x + n1 * cs.x) * post));
        o4.z = __uint_as_float(f2tf((n2 * cs.y - n3 * sn.y) * post));
        o4.w = __uint_as_float(f2tf((n2 * sn.y + n3 * cs.y) * post));
        *(float4*)(buf + rowbase + h * HD + lane * 4) = o4;
    }
}

// ---------------- flash attention: Q-frags in regs, double-buffered K/V ----------------
#define QLD 132
#define KLD 132
#define VTLD 68
#define PLD 68
#define KBUF (64 * KLD)
#define VBUF (128 * VTLD)
#define VS_OFF (2 * KBUF)
#define PS_OFF (2 * KBUF + 2 * VBUF)
#define ATTN_SMEM ((PS_OFF + 128 * PLD) * 4)

__global__ __launch_bounds__(256) void attn_mma(
    const float* __restrict__ Q, const float* __restrict__ K,
    const float* __restrict__ Vt, float* __restrict__ O)
{
    extern __shared__ float sm[];
    float* Ps = sm + PS_OFF;

    const int t = threadIdx.x;
    const int lane = t & 31, w = t >> 5;
    const int g = lane >> 2, tig = lane & 3;
    const int mb = w * 16;
    const int m0 = blockIdx.x * 128;
    const int h = blockIdx.y;
    const int b = blockIdx.z;
    const size_t seqbase = (size_t)b * SEQ;

    const unsigned smb = s2u(sm);
    const unsigned k_base = smb;
    const unsigned v_base = smb + VS_OFF * 4;
    const unsigned p_lm = smb + PS_OFF * 4 +
        (unsigned)((((mb + (lane & 15)) * PLD + ((lane >> 4) << 2))) * 4);
    const unsigned k_lm = k_base +
        (unsigned)(((((lane & 7) + ((lane >> 4) << 3)) * KLD + (((lane >> 3) & 1) << 2))) * 4);
    const unsigned v_lm = v_base +
        (unsigned)(((((lane & 7) + ((lane >> 4) << 3)) * VTLD + (((lane >> 3) & 1) << 2))) * 4);

    {
        float* Qs = sm;
        const float* Qg = Q + (seqbase + m0) * DIMN + h * HD;
        for (int i = t; i < 128 * 32; i += 256) {
            int r = i >> 5, c4 = (i & 31) << 2;
            *(float4*)(Qs + r * QLD + c4) = *(const float4*)(Qg + (size_t)r * DIMN + c4);
        }
    }
    __syncthreads();
    unsigned qf[16][4];
    {
        const unsigned q_lm = smb +
            (unsigned)((((mb + (lane & 15)) * QLD + ((lane >> 4) << 2))) * 4);
        #pragma unroll
        for (int kk = 0; kk < 16; kk++)
            ldm_x4(qf[kk][0], qf[kk][1], qf[kk][2], qf[kk][3], q_lm + (unsigned)(kk * 32));
    }
    __syncthreads();

    const float* VgT = Vt + ((size_t)(b * HEADS + h) * HD) * SEQ;
    {
        const float* Kg = K + seqbase * DIMN + h * HD;
        #pragma unroll
        for (int j = 0; j < 8; j++) {
            int idx = j * 256 + t;
            int r = idx >> 5, c = (idx & 31) << 2;
            cpa16(k_base + (unsigned)((r * KLD + c) * 4), Kg + (size_t)r * DIMN + c);
        }
        cp_commit();
        #pragma unroll
        for (int j = 0; j < 8; j++) {
            int idx = j * 256 + t;
            int r = idx >> 4, c = (idx & 15) << 2;
            cpa16(v_base + (unsigned)((r * VTLD + c) * 4), VgT + (size_t)r * SEQ + c);
        }
        cp_commit();
    }

    float m0r = -1e30f, m1r = -1e30f, l0 = 0.f, l1 = 0.f;
    float o[16][4];
    #pragma unroll
    for (int nt = 0; nt < 16; nt++)
        #pragma unroll
        for (int i = 0; i < 4; i++) o[nt][i] = 0.f;

    for (int n = 0; n < SEQ / 64; n++) {
        const int n0 = n * 64;
        const int kb = n & 1;
        const bool has_next = (n + 1 < SEQ / 64);

        cp_wait<1>();
        __syncthreads();

        if (has_next) {
            const float* Kg = K + (seqbase + n0 + 64) * DIMN + h * HD;
            unsigned kd = k_base + (unsigned)((1 - kb) * KBUF * 4);
            #pragma unroll
            for (int j = 0; j < 8; j++) {
                int idx = j * 256 + t;
                int r = idx >> 5, c = (idx & 31) << 2;
                cpa16(kd + (unsigned)((r * KLD + c) * 4), Kg + (size_t)r * DIMN + c);
            }
            cp_commit();
        }

        float s[8][4];
        #pragma unroll
        for (int nt = 0; nt < 8; nt++)
            #pragma unroll
            for (int i = 0; i < 4; i++) s[nt][i] = 0.f;
        const unsigned k_cur = k_lm + (unsigned)(kb * KBUF * 4);
        #pragma unroll
        for (int kk = 0; kk < 16; kk++) {
            #pragma unroll
            for (int ntp = 0; ntp < 4; ntp++) {
                unsigned b0, b1, b2, b3;
                ldm_x4(b0, b1, b2, b3, k_cur + (unsigned)(ntp * 16 * KLD * 4 + kk * 32));
                mma_tf32(s[2*ntp][0], s[2*ntp][1], s[2*ntp][2], s[2*ntp][3],
                         qf[kk][0], qf[kk][1], qf[kk][2], qf[kk][3], b0, b1);
                mma_tf32(s[2*ntp+1][0], s[2*ntp+1][1], s[2*ntp+1][2], s[2*ntp+1][3],
                         qf[kk][0], qf[kk][1], qf[kk][2], qf[kk][3], b2, b3);
            }
        }

        float mx0 = -1e30f, mx1 = -1e30f;
        #pragma unroll
        for (int nt = 0; nt < 8; nt++) {
            mx0 = fmaxf(mx0, fmaxf(s[nt][0], s[nt][1]));
            mx1 = fmaxf(mx1, fmaxf(s[nt][2], s[nt][3]));
        }
        mx0 = fmaxf(mx0, __shfl_xor_sync(0xffffffffu, mx0, 1));
        mx0 = fmaxf(mx0, __shfl_xor_sync(0xffffffffu, mx0, 2));
        mx1 = fmaxf(mx1, __shfl_xor_sync(0xffffffffu, mx1, 1));
        mx1 = fmaxf(mx1, __shfl_xor_sync(0xffffffffu, mx1, 2));
        float mn0 = fmaxf(m0r, mx0), mn1 = fmaxf(m1r, mx1);
        float sc0 = __expf(m0r - mn0), sc1 = __expf(m1r - mn1);
        m0r = mn0; m1r = mn1;
        float sum0 = 0.f, sum1 = 0.f;
        #pragma unroll
        for (int nt = 0; nt < 8; nt++) {
            s[nt][0] = __expf(s[nt][0] - mn0); sum0 += s[nt][0];
            s[nt][1] = __expf(s[nt][1] - mn0); sum0 += s[nt][1];
            s[nt][2] = __expf(s[nt][2] - mn1); sum1 += s[nt][2];
            s[nt][3] = __expf(s[nt][3] - mn1); sum1 += s[nt][3];
        }
        sum0 += __shfl_xor_sync(0xffffffffu, sum0, 1);
        sum0 += __shfl_xor_sync(0xffffffffu, sum0, 2);
        sum1 += __shfl_xor_sync(0xffffffffu, sum1, 1);
        sum1 += __shfl_xor_sync(0xffffffffu, sum1, 2);
        l0 = l0 * sc0 + sum0;
        l1 = l1 * sc1 + sum1;

        #pragma unroll
        for (int nt = 0; nt < 8; nt++) {
            *(float2*)(Ps + (mb + g) * PLD + nt * 8 + 2 * tig) =
                make_float2(__uint_as_float(f2tf(s[nt][0])), __uint_as_float(f2tf(s[nt][1])));
            *(float2*)(Ps + (mb + g + 8) * PLD + nt * 8 + 2 * tig) =
                make_float2(__uint_as_float(f2tf(s[nt][2])), __uint_as_float(f2tf(s[nt][3])));
        }
        #pragma unroll
        for (int nt = 0; nt < 16; nt++) {
            o[nt][0] *= sc0; o[nt][1] *= sc0;
            o[nt][2] *= sc1; o[nt][3] *= sc1;
        }
        __syncwarp();

        if (has_next) cp_wait<1>(); else cp_wait<0>();
        __syncthreads();

        if (has_next) {
            unsigned vd = v_base + (unsigned)((1 - kb) * VBUF * 4);
            #pragma unroll
            for (int j = 0; j < 8; j++) {
                int idx = j * 256 + t;
                int r = idx >> 4, c = (idx & 15) << 2;
                cpa16(vd + (unsigned)((r * VTLD + c) * 4),
                      VgT + (size_t)r * SEQ + n0 + 64 + c);
            }
            cp_commit();
        }

        const unsigned v_cur = v_lm + (unsigned)(kb * VBUF * 4);
        #pragma unroll
        for (int kk = 0; kk < 8; kk++) {
            unsigned a0, a1, a2, a3;
            ldm_x4(a0, a1, a2, a3, p_lm + (unsigned)(kk * 32));
            #pragma unroll
            for (int ntp = 0; ntp < 8; ntp++) {
                unsigned b0, b1, b2, b3;
                ldm_x4(b0, b1, b2, b3, v_cur + (unsigned)(ntp * 16 * VTLD * 4 + kk * 32));
                mma_tf32(o[2*ntp][0], o[2*ntp][1], o[2*ntp][2], o[2*ntp][3],
                         a0, a1, a2, a3, b0, b1);
                mma_tf32(o[2*ntp+1][0], o[2*ntp+1][1], o[2*ntp+1][2], o[2*ntp+1][3],
                         a0, a1, a2, a3, b2, b3);
            }
        }
    }

    float inv0 = 1.f / l0, inv1 = 1.f / l1;
    float* Og = O + (seqbase + m0 + mb) * DIMN + h * HD;
    #pragma unroll
    for (int nt = 0; nt < 16; nt++) {
        int col = nt * 8 + 2 * tig;
        *(float2*)(Og + (size_t)g * DIMN + col) =
            make_float2(__uint_as_float(f2tf(o[nt][0] * inv0)),
                        __uint_as_float(f2tf(o[nt][1] * inv0)));
        *(float2*)(Og + (size_t)(g + 8) * DIMN + col) =
            make_float2(__uint_as_float(f2tf(o[nt][2] * inv1)),
                        __uint_as_float(f2tf(o[nt][3] * inv1)));
    }
}

// ---------------- launch ----------------
extern "C" void kernel_launch(void* const* d_in, const int* in_sizes, int n_in,
                              void* d_out, int out_size)
{
    const float* x        = (const float*)d_in[0];
    const float* ctx      = (const float*)d_in[1];
    const float* rope_cos = (const float*)d_in[2];
    const float* rope_sin = (const float*)d_in[3];
    const float* wq   = (const float*)d_in[4];
    const float* bq   = (const float*)d_in[5];
    const float* wk   = (const float*)d_in[6];
    const float* bk   = (const float*)d_in[7];
    const float* wv   = (const float*)d_in[8];
    const float* bv   = (const float*)d_in[9];
    const float* wqc  = (const float*)d_in[10];
    const float* bqc  = (const float*)d_in[11];
    const float* wkc  = (const float*)d_in[12];
    const float* bkc  = (const float*)d_in[13];
    const float* wvc  = (const float*)d_in[14];
    const float* bvc  = (const float*)d_in[15];
    const float* w_out     = (const float*)d_in[16];
    const float* b_out     = (const float*)d_in[17];
    const float* w_add_out = (const float*)d_in[18];
    const float* b_add_out = (const float*)d_in[19];
    const float* g_q  = (const float*)d_in[20];
    const float* g_k  = (const float*)d_in[21];
    const float* g_qc = (const float*)d_in[22];
    const float* g_kc = (const float*)d_in[23];
    float* out = (float*)d_out;

    float *qb, *kb, *vtb, *ob, *wtf, *xtf, *ctxtf;
    cudaGetSymbolAddress((void**)&qb, g_qbuf);
    cudaGetSymbolAddress((void**)&kb, g_kbuf);
    cudaGetSymbolAddress((void**)&vtb, g_vtbuf);
    cudaGetSymbolAddress((void**)&ob, g_obuf);
    cudaGetSymbolAddress((void**)&wtf, g_wtf);
    cudaGetSymbolAddress((void**)&xtf, g_xtf);
    cudaGetSymbolAddress((void**)&ctxtf, g_ctxtf);

    const int smem_gemm = (NSTAGE * ASTAGE + NSTAGE * BSTAGE) * 4;   // 110592
    cudaFuncSetAttribute(gemm_tf32, cudaFuncAttributeMaxDynamicSharedMemorySize, smem_gemm);
    cudaFuncSetAttribute(attn_mma, cudaFuncAttributeMaxDynamicSharedMemorySize, ATTN_SMEM);

    // ---- pre-pass: transpose+cvt weights (float4 both sides); cvt activations ----
    WtCfg wc;
    const float* wsrc[8] = {wq, wk, wv, wqc, wkc, wvc, w_out, w_add_out};
    for (int i = 0; i < 8; i++) { wc.in[i] = wsrc[i]; wc.out[i] = wtf + (size_t)i * M2; }
    wtrans_cvt<<<dim3(DIMN / 128, DIMN / 32, 8), 256>>>(wc);

    CvAll cv;
    cv.in[0] = x;   cv.out[0] = xtf;   cv.n4[0] = BATCH * S_IMG * DIMN / 4;
    cv.in[1] = ctx; cv.out[1] = ctxtf; cv.n4[1] = BATCH * S_TXT * DIMN / 4;
    cvt_all<<<dim3(592, 2), 256>>>(cv);

    // ---- fused QKV (ctx half: y<8, img half: y>=8), z = Q/K/V ----
    GemmCfg q1;
    q1.A[0] = ctxtf; q1.A[1] = xtf;
    q1.W[0] = wtf + 3 * (size_t)M2; q1.W[1] = wtf + 4 * (size_t)M2; q1.W[2] = wtf + 5 * (size_t)M2;
    q1.W[3] = wtf + 0 * (size_t)M2; q1.W[4] = wtf + 1 * (size_t)M2; q1.W[5] = wtf + 2 * (size_t)M2;
    q1.bias[0] = bqc; q1.bias[1] = bkc; q1.bias[2] = bvc;
    q1.bias[3] = bq;  q1.bias[4] = bk;  q1.bias[5] = bv;
    q1.C[0] = qb; q1.C[1] = kb; q1.C[2] = vtb;
    q1.C[3] = qb; q1.C[4] = kb; q1.C[5] = vtb;
    q1.S[0] = S_TXT; q1.isb[0] = S_TXT; q1.ioff[0] = 0; q1.osb[0] = SEQ; q1.ooff[0] = 0;
    q1.S[1] = S_IMG; q1.isb[1] = S_IMG; q1.ioff[1] = 0; q1.osb[1] = SEQ; q1.ooff[1] = S_TXT;
    q1.ysplit = (BATCH * S_TXT) / 128;    // 8
    q1.cvt_mask = 4; q1.vt_mask = 4;
    gemm_tf32<<<dim3(DIMN / 128, 24, 3), 256, smem_gemm>>>(q1);

    dim3 grid_rr(SEQ, BATCH);
    rmsrope_kernel<<<grid_rr, 256>>>(qb, kb, rope_cos, rope_sin, g_q, g_qc, g_k, g_kc);

    dim3 grid_at(SEQ / 128, HEADS, BATCH);
    attn_mma<<<grid_at, 256, ATTN_SMEM>>>(qb, kb, vtb, ob);

    // ---- fused output projections (txt half: y<8, img half: y>=8) ----
    GemmCfg q2;
    q2.A[0] = ob; q2.A[1] = ob;
    q2.W[0] = wtf + 7 * (size_t)M2; q2.W[1] = q2.W[0]; q2.W[2] = q2.W[0];
    q2.W[3] = wtf + 6 * (size_t)M2; q2.W[4] = q2.W[3]; q2.W[5] = q2.W[3];
    q2.bias[0] = b_add_out; q2.bias[1] = b_add_out; q2.bias[2] = b_add_out;
    q2.bias[3] = b_out;     q2.bias[4] = b_out;     q2.bias[5] = b_out;
    q2.C[0] = out; q2.C[1] = out; q2.C[2] = out;
    q2.C[3] = out + (size_t)BATCH * S_TXT * DIMN; q2.C[4] = q2.C[3]; q2.C[5] = q2.C[3];
    q2.S[0] = S_TXT; q2.isb[0] = SEQ; q2.ioff[0] = 0;     q2.osb[0] = S_TXT; q2.ooff[0] = 0;
    q2.S[1] = S_IMG; q2.isb[1] = SEQ; q2.ioff[1] = S_TXT; q2.osb[1] = S_IMG; q2.ooff[1] = 0;
    q2.ysplit = (BATCH * S_TXT) / 128;    // 8
    q2.cvt_mask = 0; q2.vt_mask = 0;
    gemm_tf32<<<dim3(DIMN / 128, 24, 1), 256, smem_gemm>>>(q2);
}

// round 16
// speedup vs baseline: 1.0398x; 1.0398x over previous
#include <cuda_runtime.h>
#include <cuda_bf16.h>
#include <math.h>

#define DIMN 3072
#define HEADS 24
#define HD 128
#define BATCH 2
#define S_IMG 1024
#define S_TXT 512
#define SEQ 1536
#define SCALE 0.08838834764831845f   // 1/sqrt(128)
#define M2 (DIMN * DIMN)

// ---------------- scratch ----------------
__device__ float g_qbuf[(size_t)BATCH * SEQ * DIMN];
__device__ float g_kbuf[(size_t)BATCH * SEQ * DIMN];
__device__ float g_vtbuf[(size_t)BATCH * SEQ * DIMN];   // V transposed: [b][h][d][seq]
__device__ float g_obuf[(size_t)BATCH * SEQ * DIMN];
__device__ float g_wtf[(size_t)8 * M2];                 // tf32 weights [k][n]
__device__ float g_xtf[(size_t)BATCH * S_IMG * DIMN];
__device__ float g_ctxtf[(size_t)BATCH * S_TXT * DIMN];

__device__ __forceinline__ unsigned f2tf(float f) {
    unsigned u;
    asm("cvt.rna.tf32.f32 %0, %1;" : "=r"(u) : "f"(f));
    return u;
}
__device__ __forceinline__ void mma_tf32(float& d0, float& d1, float& d2, float& d3,
                                         unsigned a0, unsigned a1, unsigned a2, unsigned a3,
                                         unsigned b0, unsigned b1)
{
    asm volatile("mma.sync.aligned.m16n8k8.row.col.f32.tf32.tf32.f32 "
                 "{%0,%1,%2,%3}, {%4,%5,%6,%7}, {%8,%9}, {%0,%1,%2,%3};\n"
                 : "+f"(d0), "+f"(d1), "+f"(d2), "+f"(d3)
                 : "r"(a0), "r"(a1), "r"(a2), "r"(a3), "r"(b0), "r"(b1));
}
__device__ __forceinline__ unsigned s2u(const void* p) {
    unsigned r;
    asm("{.reg .u64 t; cvta.to.shared.u64 t, %1; cvt.u32.u64 %0, t;}" : "=r"(r) : "l"(p));
    return r;
}
__device__ __forceinline__ void cpa16(unsigned dst, const void* src) {
    asm volatile("cp.async.cg.shared.global [%0], [%1], 16;" :: "r"(dst), "l"(src));
}
__device__ __forceinline__ void cp_commit() { asm volatile("cp.async.commit_group;"); }
template <int N> __device__ __forceinline__ void cp_wait() {
    asm volatile("cp.async.wait_group %0;" :: "n"(N));
}
__device__ __forceinline__ void ldm_x4(unsigned& r0, unsigned& r1, unsigned& r2, unsigned& r3,
                                       unsigned addr)
{
    asm volatile("ldmatrix.sync.aligned.m8n8.x4.shared.b16 {%0,%1,%2,%3}, [%4];"
                 : "=r"(r0), "=r"(r1), "=r"(r2), "=r"(r3) : "r"(addr));
}

// ---------------- pre-pass: batched tf32 conversion (10 tensors, ILP x2) ----------------
struct CvAll { const float* in[10]; float* out[10]; int n4[10]; };
__global__ __launch_bounds__(256) void cvt_all(CvAll p)
{
    const float* in = p.in[blockIdx.y];
    float* out = p.out[blockIdx.y];
    const int n4 = p.n4[blockIdx.y];
    const int stride = gridDim.x * blockDim.x;
    int i = blockIdx.x * blockDim.x + threadIdx.x;
    for (; i < n4; i += 2 * stride) {
        float4 v0 = ((const float4*)in)[i];
        int i1 = i + stride;
        bool ok = i1 < n4;
        float4 v1 = ok ? ((const float4*)in)[i1] : make_float4(0.f, 0.f, 0.f, 0.f);
        float4 o0, o1;
        o0.x = __uint_as_float(f2tf(v0.x)); o0.y = __uint_as_float(f2tf(v0.y));
        o0.z = __uint_as_float(f2tf(v0.z)); o0.w = __uint_as_float(f2tf(v0.w));
        ((float4*)out)[i] = o0;
        if (ok) {
            o1.x = __uint_as_float(f2tf(v1.x)); o1.y = __uint_as_float(f2tf(v1.y));
            o1.z = __uint_as_float(f2tf(v1.z)); o1.w = __uint_as_float(f2tf(v1.w));
            ((float4*)out)[i1] = o1;
        }
    }
}

// ---------------- tf32 GEMM (round-7 body, two-half fused dispatch) ----------------
#define GA_LD 36
#define GB_LD 136
#define NSTAGE 3
#define ASTAGE (128 * GA_LD)
#define BSTAGE (32 * GB_LD)

struct GemmCfg {
    const float* A[2];
    const float* W[6];      // idx = z + 3*half
    const float* bias[6];
    float* C[6];
    int S[2], isb[2], ioff[2], osb[2], ooff[2];
    int ysplit, cvt_mask, vt_mask;
};

__global__ __launch_bounds__(256) void gemm_tf32(GemmCfg p)
{
    extern __shared__ float sm[];
    float* As = sm;
    float* Bs = sm + NSTAGE * ASTAGE;

    const int z = blockIdx.z;
    const int half = (blockIdx.y >= p.ysplit) ? 1 : 0;
    const int yy = blockIdx.y - (half ? p.ysplit : 0);
    const int wi = z + 3 * half;
    const float* A    = p.A[half];
    const float* W    = p.W[wi];
    const float* bias = p.bias[wi];
    float* C          = p.C[wi];
    const int S_part = p.S[half], in_sb = p.isb[half], in_off = p.ioff[half];
    const int out_sb = p.osb[half], out_off = p.ooff[half];
    const bool do_cvt = (p.cvt_mask >> z) & 1;
    const bool do_vt  = (p.vt_mask >> z) & 1;

    const int t = threadIdx.x;
    const int lane = t & 31, w = t >> 5;
    const int g = lane >> 2, tig = lane & 3;
    const int wm = w >> 2, wn = w & 3;          // 2x4 warps, warp tile 64x32
    const int bm = yy * 128;
    const int bn = blockIdx.x * 128;

    const float* Aptr[4];
    #pragma unroll
    for (int j = 0; j < 4; j++) {
        int r = 32 * j + (t >> 3);
        int gr = bm + r;
        int ab = gr / S_part, as_ = gr - ab * S_part;
        Aptr[j] = A + (size_t)(ab * in_sb + in_off + as_) * DIMN + ((t & 7) << 2);
    }
    const float* Bptr[4];
    #pragma unroll
    for (int j = 0; j < 4; j++) {
        int r = 8 * j + (t >> 5);
        Bptr[j] = W + (size_t)r * DIMN + bn + ((t & 31) << 2);
    }

    const unsigned a_base = s2u(As);
    const unsigned b_base = s2u(Bs);
    unsigned a_off[4], b_off[4];
    #pragma unroll
    for (int j = 0; j < 4; j++) {
        a_off[j] = a_base + (unsigned)(((32 * j + (t >> 3)) * GA_LD + ((t & 7) << 2)) * 4);
        b_off[j] = b_base + (unsigned)(((8 * j + (t >> 5)) * GB_LD + ((t & 31) << 2)) * 4);
    }
    const unsigned a_lm = a_base +
        (unsigned)((((wm * 64 + (lane & 15)) * GA_LD + ((lane >> 4) << 2))) * 4);

    const int NITER = DIMN / 32;                // 96

    #pragma unroll
    for (int s = 0; s < 2; s++) {
        int k0 = s * 32;
        #pragma unroll
        for (int j = 0; j < 4; j++) cpa16(a_off[j] + s * ASTAGE * 4, Aptr[j] + k0);
        #pragma unroll
        for (int j = 0; j < 4; j++) cpa16(b_off[j] + s * BSTAGE * 4, Bptr[j] + (size_t)k0 * DIMN);
        cp_commit();
    }

    float acc[4][4][4];
    #pragma unroll
    for (int mt = 0; mt < 4; mt++)
        #pragma unroll
        for (int nt = 0; nt < 4; nt++)
            #pragma unroll
            for (int i = 0; i < 4; i++) acc[mt][nt][i] = 0.f;

    int st = 0;
    for (int it = 0; it < NITER; it++) {
        if (it == NITER - 1) cp_wait<0>(); else cp_wait<1>();
        __syncthreads();

        const unsigned a_st = a_lm + (unsigned)(st * ASTAGE * 4);
        const float* SB = Bs + st * BSTAGE + wn * 32;
        #pragma unroll
        for (int ks = 0; ks < 4; ks++) {
            int kb = ks * 8;
            unsigned a[4][4];
            #pragma unroll
            for (int mt = 0; mt < 4; mt++)
                ldm_x4(a[mt][0], a[mt][1], a[mt][2], a[mt][3],
                       a_st + (unsigned)((mt * 16 * GA_LD + kb) * 4));
            unsigned b[4][2];
            #pragma unroll
            for (int nt = 0; nt < 4; nt++) {
                const float* pp = SB + (kb + tig) * GB_LD + nt * 8 + g;
                b[nt][0] = __float_as_uint(pp[0]);
                b[nt][1] = __float_as_uint(pp[4 * GB_LD]);
            }
            #pragma unroll
            for (int mt = 0; mt < 4; mt++)
                #pragma unroll
                for (int nt = 0; nt < 4; nt++)
                    mma_tf32(acc[mt][nt][0], acc[mt][nt][1], acc[mt][nt][2], acc[mt][nt][3],
                             a[mt][0], a[mt][1], a[mt][2], a[mt][3],
                             b[nt][0], b[nt][1]);
        }

        if (it + 2 < NITER) {
            int k0 = (it + 2) * 32;
            int ns = (st + 2) % NSTAGE;
            #pragma unroll
            for (int j = 0; j < 4; j++) cpa16(a_off[j] + ns * ASTAGE * 4, Aptr[j] + k0);
            #pragma unroll
            for (int j = 0; j < 4; j++) cpa16(b_off[j] + ns * BSTAGE * 4, Bptr[j] + (size_t)k0 * DIMN);
            cp_commit();
        }
        st = (st + 1) % NSTAGE;
    }

    #pragma unroll
    for (int mt = 0; mt < 4; mt++) {
        int r0 = bm + wm * 64 + mt * 16 + g;
        int r1 = r0 + 8;
        int cb0 = r0 / S_part, cs0 = r0 - cb0 * S_part;
        int cb1 = r1 / S_part, cs1 = r1 - cb1 * S_part;
        if (do_vt) {
            int s0 = out_off + cs0, s1 = out_off + cs1;
            #pragma unroll
            for (int nt = 0; nt < 4; nt++) {
                int col = bn + wn * 32 + nt * 8 + 2 * tig;
                int hh = col >> 7, d = col & 127;
                float bv0 = bias[col], bv1 = bias[col + 1];
                float* p0 = C + (((size_t)cb0 * HEADS + hh) * HD + d) * SEQ;
                float* p1 = C + (((size_t)cb1 * HEADS + hh) * HD + d) * SEQ;
                p0[s0]       = __uint_as_float(f2tf(acc[mt][nt][0] + bv0));
                p0[SEQ + s0] = __uint_as_float(f2tf(acc[mt][nt][1] + bv1));
                p1[s1]       = __uint_as_float(f2tf(acc[mt][nt][2] + bv0));
                p1[SEQ + s1] = __uint_as_float(f2tf(acc[mt][nt][3] + bv1));
            }
        } else {
            float* C0r = C + (size_t)(cb0 * out_sb + out_off + cs0) * DIMN;
            float* C1r = C + (size_t)(cb1 * out_sb + out_off + cs1) * DIMN;
            #pragma unroll
            for (int nt = 0; nt < 4; nt++) {
                int col = bn + wn * 32 + nt * 8 + 2 * tig;
                float bv0 = bias[col], bv1 = bias[col + 1];
                float v00 = acc[mt][nt][0] + bv0, v01 = acc[mt][nt][1] + bv1;
                float v10 = acc[mt][nt][2] + bv0, v11 = acc[mt][nt][3] + bv1;
                if (do_cvt) {
                    v00 = __uint_as_float(f2tf(v00)); v01 = __uint_as_float(f2tf(v01));
                    v10 = __uint_as_float(f2tf(v10)); v11 = __uint_as_float(f2tf(v11));
                }
                *(float2*)(C0r + col) = make_float2(v00, v01);
                *(float2*)(C1r + col) = make_float2(v10, v11);
            }
        }
    }
}

// ---------------- per-head RMSNorm + RoPE, batched (writes tf32; Q pre-scaled) ----------------
__global__ __launch_bounds__(256) void rmsrope_kernel(
    float* __restrict__ q, float* __restrict__ k,
    const float* __restrict__ cosb, const float* __restrict__ sinb,
    const float* __restrict__ gq, const float* __restrict__ gqc,
    const float* __restrict__ gk, const float* __restrict__ gkc)
{
    const int s = blockIdx.x;
    const int b = blockIdx.y;
    const int w = threadIdx.x >> 5, lane = threadIdx.x & 31;
    const size_t rowbase = ((size_t)(b * SEQ + s)) * DIMN;
    const bool txt = s < S_TXT;

    float2 cs = *(const float2*)(cosb + s * 64 + lane * 2);
    float2 sn = *(const float2*)(sinb + s * 64 + lane * 2);

    #pragma unroll
    for (int i = 0; i < 6; i++) {
        int inst = w * 6 + i;
        int which = inst / HEADS;
        int h = inst - which * HEADS;
        float* buf = which ? k : q;
        const float* gg = which ? (txt ? gkc : gk) : (txt ? gqc : gq);
        float post = which ? 1.0f : SCALE;

        float4 v = *(const float4*)(buf + rowbase + h * HD + lane * 4);
        float ss = v.x * v.x + v.y * v.y + v.z * v.z + v.w * v.w;
        #pragma unroll
        for (int o = 16; o; o >>= 1) ss += __shfl_xor_sync(0xffffffffu, ss, o);
        float r = rsqrtf(ss * (1.0f / HD) + 1e-6f);
        float4 gv = *(const float4*)(gg + lane * 4);
        float n0 = v.x * r * gv.x, n1 = v.y * r * gv.y;
        float n2 = v.z * r * gv.z, n3 = v.w * r * gv.w;
        float4 o4;
        o4.x = __uint_as_float(f2tf((n0 * cs.x - n1 * sn.x) * post));
        o4.y = __uint_as_float(f2tf((n0 * sn.x + n1 * cs.x) * post));
        o4.z = __uint_as_float(f2tf((n2 * cs.y - n3 * sn.y) * post));
        o4.w = __uint_as_float(f2tf((n2 * sn.y + n3 * cs.y) * post));
        *(float4*)(buf + rowbase + h * HD + lane * 4) = o4;
    }
}

// ---------------- flash attention: Q-frags in regs, double-buffered K/V ----------------
#define QLD 132
#define KLD 132
#define VTLD 68
#define PLD 68
#define KBUF (64 * KLD)
#define VBUF (128 * VTLD)
#define VS_OFF (2 * KBUF)
#define PS_OFF (2 * KBUF + 2 * VBUF)
#define ATTN_SMEM ((PS_OFF + 128 * PLD) * 4)

__global__ __launch_bounds__(256) void attn_mma(
    const float* __restrict__ Q, const float* __restrict__ K,
    const float* __restrict__ Vt, float* __restrict__ O)
{
    extern __shared__ float sm[];
    float* Ps = sm + PS_OFF;

    const int t = threadIdx.x;
    const int lane = t & 31, w = t >> 5;
    const int g = lane >> 2, tig = lane & 3;
    const int mb = w * 16;
    const int m0 = blockIdx.x * 128;
    const int h = blockIdx.y;
    const int b = blockIdx.z;
    const size_t seqbase = (size_t)b * SEQ;

    const unsigned smb = s2u(sm);
    const unsigned k_base = smb;
    const unsigned v_base = smb + VS_OFF * 4;
    const unsigned p_lm = smb + PS_OFF * 4 +
        (unsigned)((((mb + (lane & 15)) * PLD + ((lane >> 4) << 2))) * 4);
    const unsigned k_lm = k_base +
        (unsigned)(((((lane & 7) + ((lane >> 4) << 3)) * KLD + (((lane >> 3) & 1) << 2))) * 4);
    const unsigned v_lm = v_base +
        (unsigned)(((((lane & 7) + ((lane >> 4) << 3)) * VTLD + (((lane >> 3) & 1) << 2))) * 4);

    {
        float* Qs = sm;
        const float* Qg = Q + (seqbase + m0) * DIMN + h * HD;
        for (int i = t; i < 128 * 32; i += 256) {
            int r = i >> 5, c4 = (i & 31) << 2;
            *(float4*)(Qs + r * QLD + c4) = *(const float4*)(Qg + (size_t)r * DIMN + c4);
        }
    }
    __syncthreads();
    unsigned qf[16][4];
    {
        const unsigned q_lm = smb +
            (unsigned)((((mb + (lane & 15)) * QLD + ((lane >> 4) << 2))) * 4);
        #pragma unroll
        for (int kk = 0; kk < 16; kk++)
            ldm_x4(qf[kk][0], qf[kk][1], qf[kk][2], qf[kk][3], q_lm + (unsigned)(kk * 32));
    }
    __syncthreads();

    const float* VgT = Vt + ((size_t)(b * HEADS + h) * HD) * SEQ;
    {
        const float* Kg = K + seqbase * DIMN + h * HD;
        #pragma unroll
        for (int j = 0; j < 8; j++) {
            int idx = j * 256 + t;
            int r = idx >> 5, c = (idx & 31) << 2;
            cpa16(k_base + (unsigned)((r * KLD + c) * 4), Kg + (size_t)r * DIMN + c);
        }
        cp_commit();
        #pragma unroll
        for (int j = 0; j < 8; j++) {
            int idx = j * 256 + t;
            int r = idx >> 4, c = (idx & 15) << 2;
            cpa16(v_base + (unsigned)((r * VTLD + c) * 4), VgT + (size_t)r * SEQ + c);
        }
        cp_commit();
    }

    float m0r = -1e30f, m1r = -1e30f, l0 = 0.f, l1 = 0.f;
    float o[16][4];
    #pragma unroll
    for (int nt = 0; nt < 16; nt++)
        #pragma unroll
        for (int i = 0; i < 4; i++) o[nt][i] = 0.f;

    for (int n = 0; n < SEQ / 64; n++) {
        const int n0 = n * 64;
        const int kb = n & 1;
        const bool has_next = (n + 1 < SEQ / 64);

        cp_wait<1>();
        __syncthreads();

        if (has_next) {
            const float* Kg = K + (seqbase + n0 + 64) * DIMN + h * HD;
            unsigned kd = k_base + (unsigned)((1 - kb) * KBUF * 4);
            #pragma unroll
            for (int j = 0; j < 8; j++) {
                int idx = j * 256 + t;
                int r = idx >> 5, c = (idx & 31) << 2;
                cpa16(kd + (unsigned)((r * KLD + c) * 4), Kg + (size_t)r * DIMN + c);
            }
            cp_commit();
        }

        float s[8][4];
        #pragma unroll
        for (int nt = 0; nt < 8; nt++)
            #pragma unroll
            for (int i = 0; i < 4; i++) s[nt][i] = 0.f;
        const unsigned k_cur = k_lm + (unsigned)(kb * KBUF * 4);
        #pragma unroll
        for (int kk = 0; kk < 16; kk++) {
            #pragma unroll
            for (int ntp = 0; ntp < 4; ntp++) {
                unsigned b0, b1, b2, b3;
                ldm_x4(b0, b1, b2, b3, k_cur + (unsigned)(ntp * 16 * KLD * 4 + kk * 32));
                mma_tf32(s[2*ntp][0], s[2*ntp][1], s[2*ntp][2], s[2*ntp][3],
                         qf[kk][0], qf[kk][1], qf[kk][2], qf[kk][3], b0, b1);
                mma_tf32(s[2*ntp+1][0], s[2*ntp+1][1], s[2*ntp+1][2], s[2*ntp+1][3],
                         qf[kk][0], qf[kk][1], qf[kk][2], qf[kk][3], b2, b3);
            }
        }

        float mx0 = -1e30f, mx1 = -1e30f;
        #pragma unroll
        for (int nt = 0; nt < 8; nt++) {
            mx0 = fmaxf(mx0, fmaxf(s[nt][0], s[nt][1]));
            mx1 = fmaxf(mx1, fmaxf(s[nt][2], s[nt][3]));
        }
        mx0 = fmaxf(mx0, __shfl_xor_sync(0xffffffffu, mx0, 1));
        mx0 = fmaxf(mx0, __shfl_xor_sync(0xffffffffu, mx0, 2));
        mx1 = fmaxf(mx1, __shfl_xor_sync(0xffffffffu, mx1, 1));
        mx1 = fmaxf(mx1, __shfl_xor_sync(0xffffffffu, mx1, 2));
        float mn0 = fmaxf(m0r, mx0), mn1 = fmaxf(m1r, mx1);
        float sc0 = __expf(m0r - mn0), sc1 = __expf(m1r - mn1);
        m0r = mn0; m1r = mn1;
        float sum0 = 0.f, sum1 = 0.f;
        #pragma unroll
        for (int nt = 0; nt < 8; nt++) {
            s[nt][0] = __expf(s[nt][0] - mn0); sum0 += s[nt][0];
            s[nt][1] = __expf(s[nt][1] - mn0); sum0 += s[nt][1];
            s[nt][2] = __expf(s[nt][2] - mn1); sum1 += s[nt][2];
            s[nt][3] = __expf(s[nt][3] - mn1); sum1 += s[nt][3];
        }
        sum0 += __shfl_xor_sync(0xffffffffu, sum0, 1);
        sum0 += __shfl_xor_sync(0xffffffffu, sum0, 2);
        sum1 += __shfl_xor_sync(0xffffffffu, sum1, 1);
        sum1 += __shfl_xor_sync(0xffffffffu, sum1, 2);
        l0 = l0 * sc0 + sum0;
        l1 = l1 * sc1 + sum1;

        #pragma unroll
        for (int nt = 0; nt < 8; nt++) {
            *(float2*)(Ps + (mb + g) * PLD + nt * 8 + 2 * tig) =
                make_float2(__uint_as_float(f2tf(s[nt][0])), __uint_as_float(f2tf(s[nt][1])));
            *(float2*)(Ps + (mb + g + 8) * PLD + nt * 8 + 2 * tig) =
                make_float2(__uint_as_float(f2tf(s[nt][2])), __uint_as_float(f2tf(s[nt][3])));
        }
        #pragma unroll
        for (int nt = 0; nt < 16; nt++) {
            o[nt][0] *= sc0; o[nt][1] *= sc0;
            o[nt][2] *= sc1; o[nt][3] *= sc1;
        }
        __syncwarp();

        if (has_next) cp_wait<1>(); else cp_wait<0>();
        __syncthreads();

        if (has_next) {
            unsigned vd = v_base + (unsigned)((1 - kb) * VBUF * 4);
            #pragma unroll
            for (int j = 0; j < 8; j++) {
                int idx = j * 256 + t;
                int r = idx >> 4, c = (idx & 15) << 2;
                cpa16(vd + (unsigned)((r * VTLD + c) * 4),
                      VgT + (size_t)r * SEQ + n0 + 64 + c);
            }
            cp_commit();
        }

        const unsigned v_cur = v_lm + (unsigned)(kb * VBUF * 4);
        #pragma unroll
        for (int kk = 0; kk < 8; kk++) {
            unsigned a0, a1, a2, a3;
            ldm_x4(a0, a1, a2, a3, p_lm + (unsigned)(kk * 32));
            #pragma unroll
            for (int ntp = 0; ntp < 8; ntp++) {
                unsigned b0, b1, b2, b3;
                ldm_x4(b0, b1, b2, b3, v_cur + (unsigned)(ntp * 16 * VTLD * 4 + kk * 32));
                mma_tf32(o[2*ntp][0], o[2*ntp][1], o[2*ntp][2], o[2*ntp][3],
                         a0, a1, a2, a3, b0, b1);
                mma_tf32(o[2*ntp+1][0], o[2*ntp+1][1], o[2*ntp+1][2], o[2*ntp+1][3],
                         a0, a1, a2, a3, b2, b3);
            }
        }
    }

    float inv0 = 1.f / l0, inv1 = 1.f / l1;
    float* Og = O + (seqbase + m0 + mb) * DIMN + h * HD;
    #pragma unroll
    for (int nt = 0; nt < 16; nt++) {
        int col = nt * 8 + 2 * tig;
        *(float2*)(Og + (size_t)g * DIMN + col) =
            make_float2(__uint_as_float(f2tf(o[nt][0] * inv0)),
                        __uint_as_float(f2tf(o[nt][1] * inv0)));
        *(float2*)(Og + (size_t)(g + 8) * DIMN + col) =
            make_float2(__uint_as_float(f2tf(o[nt][2] * inv1)),
                        __uint_as_float(f2tf(o[nt][3] * inv1)));
    }
}

// ---------------- launch ----------------
extern "C" void kernel_launch(void* const* d_in, const int* in_sizes, int n_in,
                              void* d_out, int out_size)
{
    const float* x        = (const float*)d_in[0];
    const float* ctx      = (const float*)d_in[1];
    const float* rope_cos = (const float*)d_in[2];
    const float* rope_sin = (const float*)d_in[3];
    const float* wq   = (const float*)d_in[4];
    const float* bq   = (const float*)d_in[5];
    const float* wk   = (const float*)d_in[6];
    const float* bk   = (const float*)d_in[7];
    const float* wv   = (const float*)d_in[8];
    const float* bv   = (const float*)d_in[9];
    const float* wqc  = (const float*)d_in[10];
    const float* bqc  = (const float*)d_in[11];
    const float* wkc  = (const float*)d_in[12];
    const float* bkc  = (const float*)d_in[13];
    const float* wvc  = (const float*)d_in[14];
    const float* bvc  = (const float*)d_in[15];
    const float* w_out     = (const float*)d_in[16];
    const float* b_out     = (const float*)d_in[17];
    const float* w_add_out = (const float*)d_in[18];
    const float* b_add_out = (const float*)d_in[19];
    const float* g_q  = (const float*)d_in[20];
    const float* g_k  = (const float*)d_in[21];
    const float* g_qc = (const float*)d_in[22];
    const float* g_kc = (const float*)d_in[23];
    float* out = (float*)d_out;

    float *qb, *kb, *vtb, *ob, *wtf, *xtf, *ctxtf;
    cudaGetSymbolAddress((void**)&qb, g_qbuf);
    cudaGetSymbolAddress((void**)&kb, g_kbuf);
    cudaGetSymbolAddress((void**)&vtb, g_vtbuf);
    cudaGetSymbolAddress((void**)&ob, g_obuf);
    cudaGetSymbolAddress((void**)&wtf, g_wtf);
    cudaGetSymbolAddress((void**)&xtf, g_xtf);
    cudaGetSymbolAddress((void**)&ctxtf, g_ctxtf);

    const int smem_gemm = (NSTAGE * ASTAGE + NSTAGE * BSTAGE) * 4;
    cudaFuncSetAttribute(gemm_tf32, cudaFuncAttributeMaxDynamicSharedMemorySize, smem_gemm);
    cudaFuncSetAttribute(attn_mma, cudaFuncAttributeMaxDynamicSharedMemorySize, ATTN_SMEM);

    // ---- pre-pass: batched tf32 conversion (8 weights + x + ctx), ILP x2 ----
    CvAll cv;
    const float* wsrc[8] = {wq, wk, wv, wqc, wkc, wvc, w_out, w_add_out};
    for (int i = 0; i < 8; i++) {
        cv.in[i] = wsrc[i];
        cv.out[i] = wtf + (size_t)i * M2;
        cv.n4[i] = M2 / 4;
    }
    cv.in[8] = x;   cv.out[8] = xtf;   cv.n4[8] = BATCH * S_IMG * DIMN / 4;
    cv.in[9] = ctx; cv.out[9] = ctxtf; cv.n4[9] = BATCH * S_TXT * DIMN / 4;
    cvt_all<<<dim3(1184, 10), 256>>>(cv);

    // ---- fused QKV (ctx half: y<8, img half: y>=8), z = Q/K/V ----
    GemmCfg q1;
    q1.A[0] = ctxtf; q1.A[1] = xtf;
    q1.W[0] = wtf + 3 * (size_t)M2; q1.W[1] = wtf + 4 * (size_t)M2; q1.W[2] = wtf + 5 * (size_t)M2;
    q1.W[3] = wtf + 0 * (size_t)M2; q1.W[4] = wtf + 1 * (size_t)M2; q1.W[5] = wtf + 2 * (size_t)M2;
    q1.bias[0] = bqc; q1.bias[1] = bkc; q1.bias[2] = bvc;
    q1.bias[3] = bq;  q1.bias[4] = bk;  q1.bias[5] = bv;
    q1.C[0] = qb; q1.C[1] = kb; q1.C[2] = vtb;
    q1.C[3] = qb; q1.C[4] = kb; q1.C[5] = vtb;
    q1.S[0] = S_TXT; q1.isb[0] = S_TXT; q1.ioff[0] = 0; q1.osb[0] = SEQ; q1.ooff[0] = 0;
    q1.S[1] = S_IMG; q1.isb[1] = S_IMG; q1.ioff[1] = 0; q1.osb[1] = SEQ; q1.ooff[1] = S_TXT;
    q1.ysplit = (BATCH * S_TXT) / 128;    // 8
    q1.cvt_mask = 4; q1.vt_mask = 4;
    gemm_tf32<<<dim3(DIMN / 128, 24, 3), 256, smem_gemm>>>(q1);

    dim3 grid_rr(SEQ, BATCH);
    rmsrope_kernel<<<grid_rr, 256>>>(qb, kb, rope_cos, rope_sin, g_q, g_qc, g_k, g_kc);

    dim3 grid_at(SEQ / 128, HEADS, BATCH);
    attn_mma<<<grid_at, 256, ATTN_SMEM>>>(qb, kb, vtb, ob);

    // ---- fused output projections (txt half: y<8, img half: y>=8) ----
    GemmCfg q2;
    q2.A[0] = ob; q2.A[1] = ob;
    q2.W[0] = wtf + 7 * (size_t)M2; q2.W[1] = q2.W[0]; q2.W[2] = q2.W[0];
    q2.W[3] = wtf + 6 * (size_t)M2; q2.W[4] = q2.W[3]; q2.W[5] = q2.W[3];
    q2.bias[0] = b_add_out; q2.bias[1] = b_add_out; q2.bias[2] = b_add_out;
    q2.bias[3] = b_out;     q2.bias[4] = b_out;     q2.bias[5] = b_out;
    q2.C[0] = out; q2.C[1] = out; q2.C[2] = out;
    q2.C[3] = out + (size_t)BATCH * S_TXT * DIMN; q2.C[4] = q2.C[3]; q2.C[5] = q2.C[3];
    q2.S[0] = S_TXT; q2.isb[0] = SEQ; q2.ioff[0] = 0;     q2.osb[0] = S_TXT; q2.ooff[0] = 0;
    q2.S[1] = S_IMG; q2.isb[1] = SEQ; q2.ioff[1] = S_TXT; q2.osb[1] = S_IMG; q2.ooff[1] = 0;
    q2.ysplit = (BATCH * S_TXT) / 128;    // 8
    q2.cvt_mask = 0; q2.vt_mask = 0;
    gemm_tf32<<<dim3(DIMN / 128, 24, 1), 256, smem_gemm>>>(q2);
}